// round 8
// baseline (speedup 1.0000x reference)
#include <cuda_runtime.h>

#define BATCH 64
#define CH 3
#define IMG 640
#define PH 20
#define POOL 32
#define KDIM 1200
#define NQ 300
#define NCCOLS 84
#define NTOT 25200          // NQ * NCCOLS
#define TOPK 150
#define BT 32               // batch tile per GEMM block
#define PAIRS (BT / 2)      // f32x2-packed batch pairs
#define KCMAX 248           // Eigen threaded kc: (16384-192)/64=253 -> 248 (kr=8)
#define NPANEL 5            // panels 248,248,248,248,208

__device__ float g_pooled[BATCH * KDIM];
__device__ float g_y[BATCH * NTOT];          // 6.45 MB
__device__ float g_scores[BATCH * NQ];
__device__ int   g_ids[BATCH * NQ];

typedef unsigned long long ull;

__device__ __forceinline__ ull pack2(float lo, float hi) {
    ull r; asm("mov.b64 %0, {%1, %2};" : "=l"(r) : "f"(lo), "f"(hi)); return r;
}
__device__ __forceinline__ ull dup2(float w) {
    ull r; asm("mov.b64 %0, {%1, %1};" : "=l"(r) : "f"(w)); return r;
}
__device__ __forceinline__ void fma2(ull& acc, ull a, ull b) {
    asm("fma.rn.f32x2 %0, %1, %2, %0;" : "+l"(acc) : "l"(a), "l"(b));
}
__device__ __forceinline__ ull add2(ull a, ull b) {
    ull r; asm("add.rn.f32x2 %0, %1, %2;" : "=l"(r) : "l"(a), "l"(b)); return r;
}
__device__ __forceinline__ void unpack2(ull v, float& lo, float& hi) {
    asm("mov.b64 {%0, %1}, %2;" : "=f"(lo), "=f"(hi) : "l"(v));
}

// ---------------------------------------------------------------------------
// Kernel 1: 32x32 mean pool + BGR flip, replicating XLA *after* algebraic
// simplification:
//   div(x,255) -> mul(x, fl(1/255)) is hoisted out of the add-reduce and
//   combined with mean's *2^-10, so:
//     pooled = fl( exact_int_sum * fl(1/261120) )
//   (fl(sum*fl(1/255))*2^-10 == fl(sum*fl(1/261120)); power-of-2 scaling is
//   exact, so constant folding doesn't change bits.)
// The inner sum of integer-valued f32 (<= 261120 < 2^24) is EXACT and thus
// order-independent -> integer warp reduction, one warp per pooled cell.
// ---------------------------------------------------------------------------
__global__ void pool_kernel(const int* __restrict__ x) {
    int warp = (blockIdx.x * blockDim.x + threadIdx.x) >> 5;
    int lane = threadIdx.x & 31;
    if (warp >= BATCH * CH * PH * PH) return;
    int pw = warp % PH;
    int ph = (warp / PH) % PH;
    int c  = (warp / (PH * PH)) % CH;
    int b  = warp / (PH * PH * CH);
    int c_in = 2 - c;  // BGR flip
    const int* base = x + (((long)(b * CH + c_in) * IMG + ph * POOL) * IMG) + pw * POOL;
    int rowoff = lane >> 3;        // 0..3
    int coloff = (lane & 7) * 4;   // 0,4,..,28 (ints)
    int sum = 0;
#pragma unroll
    for (int r = 0; r < POOL; r += 4) {
        int4 v = *(const int4*)(base + (r + rowoff) * IMG + coloff);
        sum += v.x + v.y + v.z + v.w;
    }
#pragma unroll
    for (int s = 16; s; s >>= 1) sum += __shfl_xor_sync(0xffffffffu, sum, s);
    if (lane == 0)
        g_pooled[b * KDIM + c * (PH * PH) + ph * PH + pw] =
            (float)sum * (1.0f / 261120.0f);   // fl(1/261120), single rounding
}

// ---------------------------------------------------------------------------
// Kernel 2: y[b,n] = sum_k pooled[b,k] * W[k,n], replicating Eigen GEBP
// (threaded blocking, NEON mr=12/nr=4, L1=16KB default): kc=248 ->
// 5 K-panels (248,248,248,248,208); within a panel one ascending-k fused-FMA
// chain from 0; panels merged in order ((((p1+p2)+p3)+p4)+p5), each merge a
// single IEEE fp32 add. Batch pairs packed into f32x2 (element-wise fma.rn
// == scalar rounding). Smem tile = one panel, [k][pair] interleaved so
// LDS.128 fetches 2 pairs per instruction.
// ---------------------------------------------------------------------------
__global__ void __launch_bounds__(128) gemm_kernel(const float* __restrict__ W) {
    __shared__ ulonglong2 p_s[KCMAX][PAIRS / 2];
    int n  = blockIdx.x * 128 + threadIdx.x;
    int b0 = blockIdx.y * BT;
    bool active = (n < NTOT);

    ull accC[PAIRS], accP[PAIRS];
#pragma unroll
    for (int i = 0; i < PAIRS; i++) accC[i] = 0ull;

    int k0 = 0;
    for (int pan = 0; pan < NPANEL; pan++) {
        int len = (pan == NPANEL - 1) ? (KDIM - (NPANEL - 1) * KCMAX) : KCMAX; // 208 last
        __syncthreads();
        ull* ps = (ull*)p_s;
        for (int idx = threadIdx.x; idx < len * PAIRS; idx += 128) {
            int kk = idx / PAIRS, pp = idx % PAIRS;
            float a = g_pooled[(b0 + 2 * pp)     * KDIM + k0 + kk];
            float b = g_pooled[(b0 + 2 * pp + 1) * KDIM + k0 + kk];
            ps[kk * PAIRS + pp] = pack2(a, b);
        }
        __syncthreads();
#pragma unroll
        for (int i = 0; i < PAIRS; i++) accP[i] = 0ull;
        if (active) {
            const float* wp = W + (long)k0 * NTOT + n;
            for (int kk = 0; kk < len; kk += 4) {
                float w0 = wp[0];
                float w1 = wp[NTOT];
                float w2 = wp[2 * NTOT];
                float w3 = wp[3 * NTOT];
                wp += 4 * (long)NTOT;
                ull W0 = dup2(w0), W1 = dup2(w1), W2 = dup2(w2), W3 = dup2(w3);
#pragma unroll
                for (int h = 0; h < PAIRS / 2; h++) {
                    ulonglong2 q0 = p_s[kk + 0][h];
                    ulonglong2 q1 = p_s[kk + 1][h];
                    ulonglong2 q2 = p_s[kk + 2][h];
                    ulonglong2 q3 = p_s[kk + 3][h];
                    // strictly ascending k within each pair's chain
                    fma2(accP[2 * h], q0.x, W0);
                    fma2(accP[2 * h], q1.x, W1);
                    fma2(accP[2 * h], q2.x, W2);
                    fma2(accP[2 * h], q3.x, W3);
                    fma2(accP[2 * h + 1], q0.y, W0);
                    fma2(accP[2 * h + 1], q1.y, W1);
                    fma2(accP[2 * h + 1], q2.y, W2);
                    fma2(accP[2 * h + 1], q3.y, W3);
                }
            }
#pragma unroll
            for (int i = 0; i < PAIRS; i++) accC[i] = add2(accC[i], accP[i]);
        }
        k0 += len;
    }
    if (active) {
#pragma unroll
        for (int pp = 0; pp < PAIRS; pp++) {
            float ya, yb;
            unpack2(accC[pp], ya, yb);
            g_y[(long)(b0 + 2 * pp)     * NTOT + n] = ya;
            g_y[(long)(b0 + 2 * pp + 1) * NTOT + n] = yb;
        }
    }
}

// ---------------------------------------------------------------------------
// Kernel 3: per (b,q): max & argmax over 80 class scores (cols 4..83).
// One warp per (b,q); ties -> lower index (matches jnp.argmax).
// ---------------------------------------------------------------------------
__global__ void score_kernel() {
    int warp = (blockIdx.x * blockDim.x + threadIdx.x) >> 5;
    int lane = threadIdx.x & 31;
    if (warp >= BATCH * NQ) return;
    const float* row = g_y + (long)warp * NCCOLS;
    float best = -3.4e38f;
    int bidx = 0x7fffffff;
    for (int j = lane; j < 80; j += 32) {
        float v = row[4 + j];
        if (v > best) { best = v; bidx = j; }
    }
#pragma unroll
    for (int s = 16; s; s >>= 1) {
        float ov = __shfl_xor_sync(0xffffffffu, best, s);
        int   oi = __shfl_xor_sync(0xffffffffu, bidx, s);
        if (ov > best || (ov == best && oi < bidx)) { best = ov; bidx = oi; }
    }
    if (lane == 0) { g_scores[warp] = best; g_ids[warp] = bidx; }
}

// ---------------------------------------------------------------------------
// Kernel 4: per-batch stable top-150 by rank counting (descending,
// ties by lower index — matches lax.top_k). One block per batch.
// ---------------------------------------------------------------------------
__global__ void topk_kernel(float* __restrict__ out) {
    __shared__ float s[NQ];
    int b = blockIdx.x;
    for (int q = threadIdx.x; q < NQ; q += blockDim.x) s[q] = g_scores[b * NQ + q];
    __syncthreads();
    for (int q = threadIdx.x; q < NQ; q += blockDim.x) {
        float v = s[q];
        int rank = 0;
        for (int j = 0; j < NQ; j++) {
            float u = s[j];
            rank += (u > v) || (u == v && j < q);
        }
        if (rank < TOPK) {
            float* o = out + (long)(b * TOPK + rank) * 6;
            const float* yrow = g_y + ((long)b * NQ + q) * NCCOLS;
            o[0] = yrow[0];
            o[1] = yrow[1];
            o[2] = yrow[2];
            o[3] = yrow[3];
            o[4] = v;
            o[5] = (float)g_ids[b * NQ + q];
        }
    }
}

extern "C" void kernel_launch(void* const* d_in, const int* in_sizes, int n_in,
                              void* d_out, int out_size) {
    const int*   x = (const int*)d_in[0];
    const float* W = (const float*)d_in[1];
    float* out = (float*)d_out;

    // 76800 pooled cells, one warp each, 8 warps/block
    pool_kernel<<<(BATCH * CH * PH * PH) / 8, 256>>>(x);

    dim3 gg((NTOT + 127) / 128, BATCH / BT);   // (197, 2)
    gemm_kernel<<<gg, 128>>>(W);

    score_kernel<<<(BATCH * NQ * 32 + 255) / 256, 256>>>();

    topk_kernel<<<BATCH, 256>>>(out);
}